// round 2
// baseline (speedup 1.0000x reference)
#include <cuda_runtime.h>
#include <math.h>

#define D        256
#define MAXN     32768
#define MAXM     8192
#define TILE     128
#define INFBITS  0x7F800000u
#define MARGIN_F 0.075f

// ---------------- scratch (__device__ globals: no allocations allowed) ----------------
__device__ unsigned g_keys[MAXN];
__device__ unsigned g_kth;
__device__ int      g_needTies;
__device__ int      g_counter;
__device__ int      g_is64;
__device__ int      g_selidx[MAXM];
__device__ float    g_emb[MAXM * D];
__device__ int      g_lab[MAXM];
__device__ float    g_sqn[MAXM];
__device__ float    g_hp[MAXM];
__device__ int      g_poscnt[MAXM];
__device__ unsigned g_negmin[MAXM];
__device__ unsigned g_shnmin[MAXM];

// ---------------- init ----------------
__global__ void init_kernel(int MPAD) {
    int i = blockIdx.x * blockDim.x + threadIdx.x;
    if (i < MPAD) { g_negmin[i] = INFBITS; g_shnmin[i] = INFBITS; }
    if (i == 0) g_counter = 0;
}

// ---------------- monotone key map ----------------
__global__ void keys_kernel(const float* __restrict__ conf, int N) {
    for (int i = blockIdx.x * blockDim.x + threadIdx.x; i < N; i += gridDim.x * blockDim.x) {
        unsigned u = __float_as_uint(conf[i]);
        u = (u & 0x80000000u) ? ~u : (u | 0x80000000u);
        g_keys[i] = u;
    }
}

// ---------------- 4-pass MSB radix select: find k-th largest key ----------------
__global__ void radix_kernel(int N, int K) {
    __shared__ unsigned hist[256];
    __shared__ unsigned spref;
    __shared__ int srem;
    if (threadIdx.x == 0) { spref = 0u; srem = K; }
    for (int pass = 0; pass < 4; pass++) {
        int shift = 24 - 8 * pass;
        if (threadIdx.x < 256) hist[threadIdx.x] = 0u;
        __syncthreads();
        unsigned pref = spref;
        unsigned maskHi = (pass == 0) ? 0u : (0xFFFFFFFFu << (shift + 8));
        for (int i = threadIdx.x; i < N; i += blockDim.x) {
            unsigned kk = g_keys[i];
            if ((kk & maskHi) == (pref & maskHi))
                atomicAdd(&hist[(kk >> shift) & 255], 1u);
        }
        __syncthreads();
        if (threadIdx.x == 0) {
            int rem = srem; unsigned cum = 0;
            for (int b = 255; b >= 0; b--) {
                unsigned h = hist[b];
                if (cum + h >= (unsigned)rem) {
                    srem = rem - (int)cum;
                    spref = pref | ((unsigned)b << shift);
                    break;
                }
                cum += h;
            }
        }
        __syncthreads();
    }
    if (threadIdx.x == 0) { g_kth = spref; g_needTies = srem; }
}

// ---------------- compact: indices with key strictly greater than kth ----------------
__global__ void compact_kernel(int N) {
    unsigned kth = g_kth;
    for (int i = blockIdx.x * blockDim.x + threadIdx.x; i < N; i += gridDim.x * blockDim.x) {
        if (g_keys[i] > kth) {
            int p = atomicAdd(&g_counter, 1);
            g_selidx[p] = i;
        }
    }
}

// ---------------- ties: JAX top_k is stable -> lowest-index equal keys win ----------------
__global__ void ties_kernel(int N) {
    unsigned kth = g_kth;
    int need = g_needTies;
    int base = g_counter;  // finalized by prior kernel (stream order)
    for (int i = blockIdx.x * blockDim.x + threadIdx.x; i < N; i += gridDim.x * blockDim.x) {
        if (g_keys[i] == kth) {
            int r = 0;
            for (int j = 0; j < i; j++) r += (g_keys[j] == kth) ? 1 : 0;
            if (r < need) g_selidx[base + r] = i;
        }
    }
}

// ---------------- detect whether tags buffer is int64 or int32 ----------------
// Scans only odd word indices < N: in-bounds for BOTH layouts. int64 little-endian
// high words of values 0..499 are all zero; int32 odd entries are mostly nonzero.
__global__ void detect_kernel(const int* __restrict__ tagsw, int N) {
    __shared__ int anybad;
    if (threadIdx.x == 0) anybad = 0;
    __syncthreads();
    for (int i = threadIdx.x * 2 + 1; i < N; i += 2 * blockDim.x)
        if (tagsw[i] != 0) anybad = 1;
    __syncthreads();
    if (threadIdx.x == 0) g_is64 = anybad ? 0 : 1;
}

// ---------------- gather selected rows, squared norms, labels; zero-pad to MPAD ----------------
__global__ void gather_kernel(const float* __restrict__ emb, const int* __restrict__ tagsw, int K) {
    __shared__ float red[256];
    int m = blockIdx.x;
    int t = threadIdx.x;
    int idx = (m < K) ? g_selidx[m] : 0;
    float v = (m < K) ? emb[(size_t)idx * D + t] : 0.f;
    g_emb[m * D + t] = v;
    red[t] = v * v;
    __syncthreads();
    for (int s = 128; s > 0; s >>= 1) {
        if (t < s) red[t] += red[t + s];
        __syncthreads();
    }
    if (t == 0) {
        g_sqn[m] = (m < K) ? red[0] : 0.f;
        int lab = -1;
        if (m < K) lab = g_is64 ? tagsw[2 * idx] : tagsw[idx];
        g_lab[m] = lab;
    }
}

// ---------------- hard positives: max same-label distance per anchor (cheap, sparse) ----------------
__global__ void hardpos_kernel(int K, int MPAD) {
    __shared__ int slab[MAXM];
    for (int i = threadIdx.x; i < K; i += blockDim.x) slab[i] = g_lab[i];
    __syncthreads();
    int w = threadIdx.x >> 5, lane = threadIdx.x & 31;
    int a = blockIdx.x * 8 + w;
    if (a >= MPAD) return;
    if (a >= K) {
        if (lane == 0) { g_hp[a] = __uint_as_float(0xFF800000u); g_poscnt[a] = 0; }
        return;
    }
    int la = slab[a];
    float na = g_sqn[a];
    const float4* ea = (const float4*)(g_emb + a * D);
    float mx = __uint_as_float(0xFF800000u);
    int cnt = 0;
    for (int j = lane; j < K; j += 32) {
        if (j != a && slab[j] == la) {
            const float4* ej = (const float4*)(g_emb + j * D);
            float dot = 0.f;
#pragma unroll 8
            for (int q = 0; q < D / 4; q++) {
                float4 x = ea[q], y = ej[q];
                dot += x.x * y.x; dot += x.y * y.y; dot += x.z * y.z; dot += x.w * y.w;
            }
            float sq = na + g_sqn[j] - 2.f * dot;
            float d = sqrtf(fmaxf(sq, 0.f));
            mx = fmaxf(mx, d);
            cnt++;
        }
    }
    for (int o = 16; o; o >>= 1) {
        mx = fmaxf(mx, __shfl_xor_sync(0xffffffffu, mx, o));
        cnt += __shfl_xor_sync(0xffffffffu, cnt, o);
    }
    if (lane == 0) {
        g_hp[a] = cnt ? mx : __uint_as_float(0xFF800000u);
        g_poscnt[a] = cnt;
    }
}

// ---------------- main fused triangular pass: distances + neg/semi-hard mins ----------------
__global__ __launch_bounds__(256, 2) void pairwise_kernel(int KSEL, int NT) {
    __shared__ float As[32][132];
    __shared__ float Bs[32][132];

    // closed-form decode of triangular tile t -> (bi, bj), bj >= bi
    int t = blockIdx.x;
    float nf = (float)NT;
    int bi = (int)(nf + 0.5f - sqrtf((nf + 0.5f) * (nf + 0.5f) - 2.0f * (float)t));
    // correct potential off-by-one from float rounding
    while (bi > 0 && bi * NT - (bi * (bi - 1)) / 2 > t) bi--;
    while ((bi + 1) * NT - ((bi + 1) * bi) / 2 <= t) bi++;
    int off = bi * NT - (bi * (bi - 1)) / 2;
    int bj = bi + (t - off);

    int tx = threadIdx.x & 15;
    int ty = threadIdx.x >> 4;

    float c[8][8];
#pragma unroll
    for (int i = 0; i < 8; i++)
#pragma unroll
        for (int j = 0; j < 8; j++) c[i][j] = 0.f;

    int r0 = threadIdx.x >> 3;          // 0..31
    int c4 = (threadIdx.x & 7) << 2;    // 0,4,...,28

    for (int kc = 0; kc < D; kc += 32) {
#pragma unroll
        for (int p = 0; p < 4; p++) {
            int row = p * 32 + r0;
            float4 va = *(const float4*)&g_emb[(bi * TILE + row) * D + kc + c4];
            float4 vb = *(const float4*)&g_emb[(bj * TILE + row) * D + kc + c4];
            As[c4 + 0][row] = va.x; As[c4 + 1][row] = va.y; As[c4 + 2][row] = va.z; As[c4 + 3][row] = va.w;
            Bs[c4 + 0][row] = vb.x; Bs[c4 + 1][row] = vb.y; Bs[c4 + 2][row] = vb.z; Bs[c4 + 3][row] = vb.w;
        }
        __syncthreads();
#pragma unroll 8
        for (int k = 0; k < 32; k++) {
            float4 a0 = *(const float4*)&As[k][ty * 4];
            float4 a1 = *(const float4*)&As[k][64 + ty * 4];
            float4 b0 = *(const float4*)&Bs[k][tx * 4];
            float4 b1 = *(const float4*)&Bs[k][64 + tx * 4];
            float av[8] = {a0.x, a0.y, a0.z, a0.w, a1.x, a1.y, a1.z, a1.w};
            float bv[8] = {b0.x, b0.y, b0.z, b0.w, b1.x, b1.y, b1.z, b1.w};
#pragma unroll
            for (int i = 0; i < 8; i++)
#pragma unroll
                for (int j = 0; j < 8; j++) c[i][j] += av[i] * bv[j];
        }
        __syncthreads();
    }

    // epilogue: dist + min-updates for both row anchors (i) and col anchors (j)
    const float INFv = __uint_as_float(INFBITS);
    int lr[8], lc[8];
#pragma unroll
    for (int i = 0; i < 4; i++) {
        lr[i] = ty * 4 + i;  lr[i + 4] = 64 + ty * 4 + i;
        lc[i] = tx * 4 + i;  lc[i + 4] = 64 + tx * 4 + i;
    }
    int gibase = bi * TILE, gjbase = bj * TILE;

    int ljv[8]; float njv[8], hjv[8], cn[8], cs[8];
#pragma unroll
    for (int j = 0; j < 8; j++) {
        int gj = gjbase + lc[j];
        ljv[j] = g_lab[gj]; njv[j] = g_sqn[gj]; hjv[j] = g_hp[gj];
        cn[j] = INFv; cs[j] = INFv;
    }

#pragma unroll
    for (int i = 0; i < 8; i++) {
        int gi = gibase + lr[i];
        int liv = g_lab[gi];
        float niv = g_sqn[gi], hiv = g_hp[gi];
        bool rowok = gi < KSEL;
        float rn = INFv, rs = INFv;
#pragma unroll
        for (int j = 0; j < 8; j++) {
            int gj = gjbase + lc[j];
            if (rowok && gj < KSEL && liv != ljv[j]) {
                float sq = niv + njv[j] - 2.f * c[i][j];
                float d = sqrtf(fmaxf(sq, 0.f));
                rn = fminf(rn, d);
                cn[j] = fminf(cn[j], d);
                if (d > hiv)    rs = fminf(rs, d);
                if (d > hjv[j]) cs[j] = fminf(cs[j], d);
            }
        }
        // reduce row mins over the 16 threads (same ty) sharing these rows
#pragma unroll
        for (int o = 8; o >= 1; o >>= 1) {
            rn = fminf(rn, __shfl_xor_sync(0xffffffffu, rn, o));
            rs = fminf(rs, __shfl_xor_sync(0xffffffffu, rs, o));
        }
        if ((threadIdx.x & 15) == 0 && rowok) {
            if (rn < INFv) atomicMin(&g_negmin[gi], __float_as_uint(rn));
            if (rs < INFv) atomicMin(&g_shnmin[gi], __float_as_uint(rs));
        }
    }

    // column mins via shared-memory reduce (reuse As storage)
    __syncthreads();
    unsigned* sN = (unsigned*)&As[0][0];
    unsigned* sS = sN + 128;
    if (threadIdx.x < 256) sN[threadIdx.x] = INFBITS;  // covers both 128-entry arrays
    __syncthreads();
#pragma unroll
    for (int j = 0; j < 8; j++) {
        if (cn[j] < INFv) atomicMin(&sN[lc[j]], __float_as_uint(cn[j]));
        if (cs[j] < INFv) atomicMin(&sS[lc[j]], __float_as_uint(cs[j]));
    }
    __syncthreads();
    if (threadIdx.x < 128) {
        int gj = gjbase + threadIdx.x;
        if (gj < KSEL) {
            unsigned a = sN[threadIdx.x], b = sS[threadIdx.x];
            if (a != INFBITS) atomicMin(&g_negmin[gj], a);
            if (b != INFBITS) atomicMin(&g_shnmin[gj], b);
        }
    }
}

// ---------------- finalize: per-anchor loss, mean over valid ----------------
__global__ void finalize_kernel(int KSEL, float* __restrict__ out) {
    __shared__ float ssum[32];
    __shared__ int scnt[32];
    float sum = 0.f; int cnt = 0;
    for (int a = threadIdx.x; a < KSEL; a += blockDim.x) {
        int pc = g_poscnt[a];
        if (pc > 0 && (KSEL - 1 - pc) > 0) {
            float hp = g_hp[a];
            unsigned sb = g_shnmin[a];
            float hn = (sb != INFBITS) ? __uint_as_float(sb) : __uint_as_float(g_negmin[a]);
            float per = hp - hn + MARGIN_F;
            if (per < 0.f) per = 0.f;
            sum += per; cnt++;
        }
    }
    for (int o = 16; o; o >>= 1) {
        sum += __shfl_xor_sync(0xffffffffu, sum, o);
        cnt += __shfl_xor_sync(0xffffffffu, cnt, o);
    }
    int w = threadIdx.x >> 5, lane = threadIdx.x & 31;
    if (lane == 0) { ssum[w] = sum; scnt[w] = cnt; }
    __syncthreads();
    if (threadIdx.x < 32) {
        int nw = blockDim.x >> 5;
        sum = (threadIdx.x < nw) ? ssum[threadIdx.x] : 0.f;
        cnt = (threadIdx.x < nw) ? scnt[threadIdx.x] : 0;
        for (int o = 16; o; o >>= 1) {
            sum += __shfl_xor_sync(0xffffffffu, sum, o);
            cnt += __shfl_xor_sync(0xffffffffu, cnt, o);
        }
        if (threadIdx.x == 0) out[0] = (cnt > 0) ? sum / (float)cnt : 0.f;
    }
}

// ---------------- launch ----------------
extern "C" void kernel_launch(void* const* d_in, const int* in_sizes, int n_in,
                              void* d_out, int out_size) {
    const float* emb   = (const float*)d_in[0];
    const int*   tagsw = (const int*)d_in[1];
    const float* conf  = (const float*)d_in[2];
    int N = in_sizes[2];
    int K = (int)(0.2 * (double)N);           // matches int(CONF_THRESHOLD * n)
    int NT = (K + TILE - 1) / TILE;
    int MPAD = NT * TILE;

    init_kernel<<<(MPAD + 255) / 256, 256>>>(MPAD);
    keys_kernel<<<64, 256>>>(conf, N);
    radix_kernel<<<1, 1024>>>(N, K);
    compact_kernel<<<64, 256>>>(N);
    ties_kernel<<<32, 256>>>(N);
    detect_kernel<<<1, 256>>>(tagsw, N);
    gather_kernel<<<MPAD, 256>>>(emb, tagsw, K);
    hardpos_kernel<<<(MPAD + 7) / 8, 256>>>(K, MPAD);
    pairwise_kernel<<<NT * (NT + 1) / 2, 256>>>(K, NT);
    finalize_kernel<<<1, 1024>>>(K, (float*)d_out);
}

// round 5
// speedup vs baseline: 1.1412x; 1.1412x over previous
#include <cuda_runtime.h>
#include <cuda_fp16.h>
#include <math.h>
#include <stdint.h>

#define D        256
#define MAXN     32768
#define MAXM     8192
#define TILE     128
#define INFBITS  0x7F800000u
#define MARGIN_F 0.075f

// ---------------- scratch (__device__ globals: no allocations allowed) ----------------
__device__ unsigned g_keys[MAXN];
__device__ unsigned g_kth;
__device__ int      g_needTies;
__device__ int      g_counter;
__device__ int      g_is64;
__device__ int      g_selidx[MAXM];
__device__ float    g_emb[MAXM * D];
__device__ __half   g_embh[MAXM * D];
__device__ __half   g_embl[MAXM * D];
__device__ int      g_lab[MAXM];
__device__ float    g_sqn[MAXM];
__device__ float    g_hp[MAXM];
__device__ int      g_poscnt[MAXM];
__device__ unsigned g_negmin[MAXM];
__device__ unsigned g_shnmin[MAXM];

// ---------------- helpers ----------------
__device__ __forceinline__ uint32_t smem_u32(const void* p) {
    uint32_t a;
    asm("{ .reg .u64 t; cvta.to.shared.u64 t, %1; cvt.u32.u64 %0, t; }" : "=r"(a) : "l"(p));
    return a;
}
#define SW128(off) ((off) ^ (((off) >> 3) & 0x70))

__device__ __forceinline__ void ldsm_x4(uint32_t& r0, uint32_t& r1, uint32_t& r2, uint32_t& r3,
                                        uint32_t addr) {
    asm volatile("ldmatrix.sync.aligned.m8n8.x4.shared.b16 {%0,%1,%2,%3}, [%4];"
                 : "=r"(r0), "=r"(r1), "=r"(r2), "=r"(r3) : "r"(addr));
}
__device__ __forceinline__ void mma16816(float& c0, float& c1, float& c2, float& c3,
                                         uint32_t a0, uint32_t a1, uint32_t a2, uint32_t a3,
                                         uint32_t b0, uint32_t b1) {
    asm volatile(
        "mma.sync.aligned.m16n8k16.row.col.f32.f16.f16.f32 "
        "{%0,%1,%2,%3}, {%4,%5,%6,%7}, {%8,%9}, {%0,%1,%2,%3};"
        : "+f"(c0), "+f"(c1), "+f"(c2), "+f"(c3)
        : "r"(a0), "r"(a1), "r"(a2), "r"(a3), "r"(b0), "r"(b1));
}

// SMEM layout (dynamic)
#define SA_H   0
#define SA_L   16384
#define SB_H   32768
#define SB_L   49152
#define SM_LABI 65536
#define SM_SQNI (SM_LABI + 512)
#define SM_HPI  (SM_SQNI + 512)
#define SM_LABJ (SM_HPI + 512)
#define SM_SQNJ (SM_LABJ + 512)
#define SM_HPJ  (SM_SQNJ + 512)
#define SM_RN   (SM_HPJ + 512)
#define SM_RS   (SM_RN + 512)
#define SM_CN   (SM_RS + 512)
#define SM_CS   (SM_CN + 512)
#define SMEM_BYTES (SM_CS + 512)

// ---------------- init ----------------
__global__ void init_kernel(int MPAD) {
    int i = blockIdx.x * blockDim.x + threadIdx.x;
    if (i < MPAD) { g_negmin[i] = INFBITS; g_shnmin[i] = INFBITS; }
    if (i == 0) g_counter = 0;
}

// ---------------- monotone key map ----------------
__global__ void keys_kernel(const float* __restrict__ conf, int N) {
    for (int i = blockIdx.x * blockDim.x + threadIdx.x; i < N; i += gridDim.x * blockDim.x) {
        unsigned u = __float_as_uint(conf[i]);
        u = (u & 0x80000000u) ? ~u : (u | 0x80000000u);
        g_keys[i] = u;
    }
}

// ---------------- 4-pass MSB radix select ----------------
__global__ void radix_kernel(int N, int K) {
    __shared__ unsigned hist[256];
    __shared__ unsigned spref;
    __shared__ int srem;
    if (threadIdx.x == 0) { spref = 0u; srem = K; }
    for (int pass = 0; pass < 4; pass++) {
        int shift = 24 - 8 * pass;
        if (threadIdx.x < 256) hist[threadIdx.x] = 0u;
        __syncthreads();
        unsigned pref = spref;
        unsigned maskHi = (pass == 0) ? 0u : (0xFFFFFFFFu << (shift + 8));
        for (int i = threadIdx.x; i < N; i += blockDim.x) {
            unsigned kk = g_keys[i];
            if ((kk & maskHi) == (pref & maskHi))
                atomicAdd(&hist[(kk >> shift) & 255], 1u);
        }
        __syncthreads();
        if (threadIdx.x == 0) {
            int rem = srem; unsigned cum = 0;
            for (int b = 255; b >= 0; b--) {
                unsigned h = hist[b];
                if (cum + h >= (unsigned)rem) {
                    srem = rem - (int)cum;
                    spref = pref | ((unsigned)b << shift);
                    break;
                }
                cum += h;
            }
        }
        __syncthreads();
    }
    if (threadIdx.x == 0) { g_kth = spref; g_needTies = srem; }
}

// ---------------- compact ----------------
__global__ void compact_kernel(int N) {
    unsigned kth = g_kth;
    for (int i = blockIdx.x * blockDim.x + threadIdx.x; i < N; i += gridDim.x * blockDim.x) {
        if (g_keys[i] > kth) {
            int p = atomicAdd(&g_counter, 1);
            g_selidx[p] = i;
        }
    }
}

// ---------------- ties (stable: lowest index wins) ----------------
__global__ void ties_kernel(int N) {
    unsigned kth = g_kth;
    int need = g_needTies;
    int base = g_counter;
    for (int i = blockIdx.x * blockDim.x + threadIdx.x; i < N; i += gridDim.x * blockDim.x) {
        if (g_keys[i] == kth) {
            int r = 0;
            for (int j = 0; j < i; j++) r += (g_keys[j] == kth) ? 1 : 0;
            if (r < need) g_selidx[base + r] = i;
        }
    }
}

// ---------------- detect int64 vs int32 tags ----------------
__global__ void detect_kernel(const int* __restrict__ tagsw, int N) {
    __shared__ int anybad;
    if (threadIdx.x == 0) anybad = 0;
    __syncthreads();
    for (int i = threadIdx.x * 2 + 1; i < N; i += 2 * blockDim.x)
        if (tagsw[i] != 0) anybad = 1;
    __syncthreads();
    if (threadIdx.x == 0) g_is64 = anybad ? 0 : 1;
}

// ---------------- gather + fp16 hi/lo split ----------------
__global__ void gather_kernel(const float* __restrict__ emb, const int* __restrict__ tagsw, int K) {
    __shared__ float red[256];
    int m = blockIdx.x;
    int t = threadIdx.x;
    int idx = (m < K) ? g_selidx[m] : 0;
    float v = (m < K) ? emb[(size_t)idx * D + t] : 0.f;
    g_emb[m * D + t] = v;
    __half hi = __float2half_rn(v);
    __half lo = __float2half_rn(v - __half2float(hi));
    g_embh[m * D + t] = hi;
    g_embl[m * D + t] = lo;
    red[t] = v * v;
    __syncthreads();
    for (int s = 128; s > 0; s >>= 1) {
        if (t < s) red[t] += red[t + s];
        __syncthreads();
    }
    if (t == 0) {
        g_sqn[m] = (m < K) ? red[0] : 0.f;
        int lab = -1;
        if (m < K) lab = g_is64 ? tagsw[2 * idx] : tagsw[idx];
        g_lab[m] = lab;
    }
}

// ---------------- hard positives (fp32 exact, sparse) ----------------
__global__ void hardpos_kernel(int K, int MPAD) {
    __shared__ int slab[MAXM];
    for (int i = threadIdx.x; i < K; i += blockDim.x) slab[i] = g_lab[i];
    __syncthreads();
    int w = threadIdx.x >> 5, lane = threadIdx.x & 31;
    int a = blockIdx.x * 8 + w;
    if (a >= MPAD) return;
    if (a >= K) {
        if (lane == 0) { g_hp[a] = __uint_as_float(0xFF800000u); g_poscnt[a] = 0; }
        return;
    }
    int la = slab[a];
    float na = g_sqn[a];
    const float4* ea = (const float4*)(g_emb + a * D);
    float mx = __uint_as_float(0xFF800000u);
    int cnt = 0;
    for (int j = lane; j < K; j += 32) {
        if (j != a && slab[j] == la) {
            const float4* ej = (const float4*)(g_emb + j * D);
            float dot = 0.f;
#pragma unroll 8
            for (int q = 0; q < D / 4; q++) {
                float4 x = ea[q], y = ej[q];
                dot += x.x * y.x; dot += x.y * y.y; dot += x.z * y.z; dot += x.w * y.w;
            }
            float sq = na + g_sqn[j] - 2.f * dot;
            float d = sqrtf(fmaxf(sq, 0.f));
            mx = fmaxf(mx, d);
            cnt++;
        }
    }
    for (int o = 16; o; o >>= 1) {
        mx = fmaxf(mx, __shfl_xor_sync(0xffffffffu, mx, o));
        cnt += __shfl_xor_sync(0xffffffffu, cnt, o);
    }
    if (lane == 0) {
        g_hp[a] = cnt ? mx : __uint_as_float(0xFF800000u);
        g_poscnt[a] = cnt;
    }
}

// ---------------- mma.sync pairwise: fp16 2-term split, fused epilogue ----------------
__global__ __launch_bounds__(256)
void pairwise_mma_kernel(int KSEL, int NT) {
    extern __shared__ char smem[];
    uint32_t sb = smem_u32(smem);
    int tid = threadIdx.x, wid = tid >> 5, lane = tid & 31;

    // triangular tile decode t -> (bi, bj), bj >= bi
    int t = blockIdx.x;
    float nf = (float)NT;
    int bi = (int)(nf + 0.5f - sqrtf((nf + 0.5f) * (nf + 0.5f) - 2.0f * (float)t));
    while (bi > 0 && bi * NT - (bi * (bi - 1)) / 2 > t) bi--;
    while ((bi + 1) * NT - ((bi + 1) * bi) / 2 <= t) bi++;
    int bj = bi + (t - (bi * NT - (bi * (bi - 1)) / 2));
    int gibase = bi * TILE, gjbase = bj * TILE;

    // aux arrays
    if (tid < 128) {
        int gi = gibase + tid, gj = gjbase + tid;
        ((int*)(smem + SM_LABI))[tid]    = g_lab[gi];
        ((float*)(smem + SM_SQNI))[tid]  = g_sqn[gi];
        ((float*)(smem + SM_HPI))[tid]   = g_hp[gi];
        ((int*)(smem + SM_LABJ))[tid]    = g_lab[gj];
        ((float*)(smem + SM_SQNJ))[tid]  = g_sqn[gj];
        ((float*)(smem + SM_HPJ))[tid]   = g_hp[gj];
        ((unsigned*)(smem + SM_RN))[tid] = INFBITS;
        ((unsigned*)(smem + SM_RS))[tid] = INFBITS;
        ((unsigned*)(smem + SM_CN))[tid] = INFBITS;
        ((unsigned*)(smem + SM_CS))[tid] = INFBITS;
    }

    int mi = wid & 1;          // 0..1 -> rows mi*64
    int nj = wid >> 1;         // 0..3 -> cols nj*32
    int R = mi * 64, C = nj * 32;

    float acc[4][4][4];
#pragma unroll
    for (int a = 0; a < 4; a++)
#pragma unroll
        for (int b = 0; b < 4; b++)
#pragma unroll
            for (int c = 0; c < 4; c++) acc[a][b][c] = 0.f;

    const uint32_t toff[4] = {SA_H, SA_L, SB_H, SB_L};

    for (int ch = 0; ch < 4; ch++) {
        // load 4 tiles (128 rows x 64 halfs, SW128 layout)
        for (int u = tid; u < 4096; u += 256) {
            int tile = u >> 10;
            int v = u & 1023;
            int row = v >> 3;
            int seg = v & 7;
            int base = (tile < 2) ? gibase : gjbase;
            const __half* src = (tile & 1) ? g_embl : g_embh;
            uint4 val = *(const uint4*)(src + (size_t)(base + row) * D + ch * 64 + seg * 8);
            *(uint4*)(smem + toff[tile] + SW128((uint32_t)(row * 128 + seg * 16))) = val;
        }
        __syncthreads();

        int lrow = lane & 15;
        int lk16 = (lane >> 4) * 16;
#pragma unroll
        for (int ks = 0; ks < 4; ks++) {
            int ko = ks * 32 + lk16;
            uint32_t ah[4][4], al[4][4], bh[2][4], bl[2][4];
#pragma unroll
            for (int mf = 0; mf < 4; mf++) {
                uint32_t addr = sb + SW128((uint32_t)((R + mf * 16 + lrow) * 128 + ko));
                ldsm_x4(ah[mf][0], ah[mf][1], ah[mf][2], ah[mf][3], SA_H + addr);
                ldsm_x4(al[mf][0], al[mf][1], al[mf][2], al[mf][3], SA_L + addr);
            }
#pragma unroll
            for (int h = 0; h < 2; h++) {
                uint32_t addr = sb + SW128((uint32_t)((C + h * 16 + lrow) * 128 + ko));
                ldsm_x4(bh[h][0], bh[h][1], bh[h][2], bh[h][3], SB_H + addr);
                ldsm_x4(bl[h][0], bl[h][1], bl[h][2], bl[h][3], SB_L + addr);
            }
#pragma unroll
            for (int mf = 0; mf < 4; mf++) {
#pragma unroll
                for (int nfr = 0; nfr < 4; nfr++) {
                    int h = nfr >> 1, s = nfr & 1;
                    uint32_t bh0 = bh[h][s], bh1 = bh[h][s + 2];
                    uint32_t bl0 = bl[h][s], bl1 = bl[h][s + 2];
                    float* cc = acc[mf][nfr];
                    mma16816(cc[0], cc[1], cc[2], cc[3],
                             ah[mf][0], ah[mf][1], ah[mf][2], ah[mf][3], bh0, bh1);
                    mma16816(cc[0], cc[1], cc[2], cc[3],
                             ah[mf][0], ah[mf][1], ah[mf][2], ah[mf][3], bl0, bl1);
                    mma16816(cc[0], cc[1], cc[2], cc[3],
                             al[mf][0], al[mf][1], al[mf][2], al[mf][3], bh0, bh1);
                }
            }
        }
        __syncthreads();
    }

    // ---------------- fused epilogue ----------------
    const float INFv = __uint_as_float(INFBITS);
    const int*   sLabI = (const int*)(smem + SM_LABI);
    const float* sSqnI = (const float*)(smem + SM_SQNI);
    const float* sHpI  = (const float*)(smem + SM_HPI);
    const int*   sLabJ = (const int*)(smem + SM_LABJ);
    const float* sSqnJ = (const float*)(smem + SM_SQNJ);
    const float* sHpJ  = (const float*)(smem + SM_HPJ);
    unsigned* sRN = (unsigned*)(smem + SM_RN);
    unsigned* sRS = (unsigned*)(smem + SM_RS);
    unsigned* sCN = (unsigned*)(smem + SM_CN);
    unsigned* sCS = (unsigned*)(smem + SM_CS);

    int lr = lane >> 2, tig = lane & 3;

    float colN[4][2], colS[4][2];
#pragma unroll
    for (int a = 0; a < 4; a++) { colN[a][0] = INFv; colN[a][1] = INFv; colS[a][0] = INFv; colS[a][1] = INFv; }

    // column meta for this lane's 8 columns
    int   cloc[4][2]; bool cok[4][2]; int clab[4][2]; float csq[4][2], chp[4][2];
#pragma unroll
    for (int nfr = 0; nfr < 4; nfr++)
#pragma unroll
        for (int p = 0; p < 2; p++) {
            int cl = C + nfr * 8 + 2 * tig + p;
            cloc[nfr][p] = cl;
            cok[nfr][p] = (gjbase + cl) < KSEL;
            clab[nfr][p] = sLabJ[cl];
            csq[nfr][p] = sSqnJ[cl];
            chp[nfr][p] = sHpJ[cl];
        }

#pragma unroll
    for (int mf = 0; mf < 4; mf++) {
        int r0 = R + mf * 16 + lr, r1 = r0 + 8;
        bool ok0 = (gibase + r0) < KSEL, ok1 = (gibase + r1) < KSEL;
        int   lab0 = sLabI[r0], lab1 = sLabI[r1];
        float sq0 = sSqnI[r0], sq1 = sSqnI[r1];
        float hp0 = sHpI[r0],  hp1 = sHpI[r1];
        float rN0 = INFv, rS0 = INFv, rN1 = INFv, rS1 = INFv;
#pragma unroll
        for (int nfr = 0; nfr < 4; nfr++) {
#pragma unroll
            for (int p = 0; p < 2; p++) {
                bool okc = cok[nfr][p];
                int lc = clab[nfr][p];
                float nc = csq[nfr][p], hc = chp[nfr][p];
                if (ok0 && okc && lab0 != lc) {
                    float sq = sq0 + nc - 2.f * acc[mf][nfr][p];
                    float dd = sqrtf(fmaxf(sq, 0.f));
                    rN0 = fminf(rN0, dd);
                    if (dd > hp0) rS0 = fminf(rS0, dd);
                    colN[nfr][p] = fminf(colN[nfr][p], dd);
                    if (dd > hc) colS[nfr][p] = fminf(colS[nfr][p], dd);
                }
                if (ok1 && okc && lab1 != lc) {
                    float sq = sq1 + nc - 2.f * acc[mf][nfr][2 + p];
                    float dd = sqrtf(fmaxf(sq, 0.f));
                    rN1 = fminf(rN1, dd);
                    if (dd > hp1) rS1 = fminf(rS1, dd);
                    colN[nfr][p] = fminf(colN[nfr][p], dd);
                    if (dd > hc) colS[nfr][p] = fminf(colS[nfr][p], dd);
                }
            }
        }
        // row reduce over the 4 lanes sharing each row (xor 1,2)
#pragma unroll
        for (int o = 1; o <= 2; o <<= 1) {
            rN0 = fminf(rN0, __shfl_xor_sync(0xffffffffu, rN0, o));
            rS0 = fminf(rS0, __shfl_xor_sync(0xffffffffu, rS0, o));
            rN1 = fminf(rN1, __shfl_xor_sync(0xffffffffu, rN1, o));
            rS1 = fminf(rS1, __shfl_xor_sync(0xffffffffu, rS1, o));
        }
        if (tig == 0) {
            if (rN0 < INFv) atomicMin(&sRN[r0], __float_as_uint(rN0));
            if (rS0 < INFv) atomicMin(&sRS[r0], __float_as_uint(rS0));
            if (rN1 < INFv) atomicMin(&sRN[r1], __float_as_uint(rN1));
            if (rS1 < INFv) atomicMin(&sRS[r1], __float_as_uint(rS1));
        }
    }
    // column reduce over lanes sharing cols (xor 4,8,16)
#pragma unroll
    for (int a = 0; a < 4; a++)
#pragma unroll
        for (int p = 0; p < 2; p++) {
#pragma unroll
            for (int o = 4; o <= 16; o <<= 1) {
                colN[a][p] = fminf(colN[a][p], __shfl_xor_sync(0xffffffffu, colN[a][p], o));
                colS[a][p] = fminf(colS[a][p], __shfl_xor_sync(0xffffffffu, colS[a][p], o));
            }
        }
    if (lane < 4) {
#pragma unroll
        for (int a = 0; a < 4; a++)
#pragma unroll
            for (int p = 0; p < 2; p++) {
                int cl = cloc[a][p];
                if (colN[a][p] < INFv) atomicMin(&sCN[cl], __float_as_uint(colN[a][p]));
                if (colS[a][p] < INFv) atomicMin(&sCS[cl], __float_as_uint(colS[a][p]));
            }
    }
    __syncthreads();
    if (tid < 128) {
        int gi = gibase + tid, gj = gjbase + tid;
        if (gi < KSEL) {
            unsigned a = sRN[tid], b = sRS[tid];
            if (a != INFBITS) atomicMin(&g_negmin[gi], a);
            if (b != INFBITS) atomicMin(&g_shnmin[gi], b);
        }
        if (gj < KSEL) {
            unsigned a = sCN[tid], b = sCS[tid];
            if (a != INFBITS) atomicMin(&g_negmin[gj], a);
            if (b != INFBITS) atomicMin(&g_shnmin[gj], b);
        }
    }
}

// ---------------- finalize ----------------
__global__ void finalize_kernel(int KSEL, float* __restrict__ out) {
    __shared__ float ssum[32];
    __shared__ int scnt[32];
    float sum = 0.f; int cnt = 0;
    for (int a = threadIdx.x; a < KSEL; a += blockDim.x) {
        int pc = g_poscnt[a];
        if (pc > 0 && (KSEL - 1 - pc) > 0) {
            float hp = g_hp[a];
            unsigned sbb = g_shnmin[a];
            float hn = (sbb != INFBITS) ? __uint_as_float(sbb) : __uint_as_float(g_negmin[a]);
            float per = hp - hn + MARGIN_F;
            if (per < 0.f) per = 0.f;
            sum += per; cnt++;
        }
    }
    for (int o = 16; o; o >>= 1) {
        sum += __shfl_xor_sync(0xffffffffu, sum, o);
        cnt += __shfl_xor_sync(0xffffffffu, cnt, o);
    }
    int w = threadIdx.x >> 5, lane = threadIdx.x & 31;
    if (lane == 0) { ssum[w] = sum; scnt[w] = cnt; }
    __syncthreads();
    if (threadIdx.x < 32) {
        int nw = blockDim.x >> 5;
        sum = (threadIdx.x < nw) ? ssum[threadIdx.x] : 0.f;
        cnt = (threadIdx.x < nw) ? scnt[threadIdx.x] : 0;
        for (int o = 16; o; o >>= 1) {
            sum += __shfl_xor_sync(0xffffffffu, sum, o);
            cnt += __shfl_xor_sync(0xffffffffu, cnt, o);
        }
        if (threadIdx.x == 0) out[0] = (cnt > 0) ? sum / (float)cnt : 0.f;
    }
}

// ---------------- launch ----------------
extern "C" void kernel_launch(void* const* d_in, const int* in_sizes, int n_in,
                              void* d_out, int out_size) {
    const float* emb   = (const float*)d_in[0];
    const int*   tagsw = (const int*)d_in[1];
    const float* conf  = (const float*)d_in[2];
    int N = in_sizes[2];
    int K = (int)(0.2 * (double)N);
    int NT = (K + TILE - 1) / TILE;
    int MPAD = NT * TILE;

    cudaFuncSetAttribute(pairwise_mma_kernel, cudaFuncAttributeMaxDynamicSharedMemorySize, SMEM_BYTES);

    init_kernel<<<(MPAD + 255) / 256, 256>>>(MPAD);
    keys_kernel<<<64, 256>>>(conf, N);
    radix_kernel<<<1, 1024>>>(N, K);
    compact_kernel<<<64, 256>>>(N);
    ties_kernel<<<32, 256>>>(N);
    detect_kernel<<<1, 256>>>(tagsw, N);
    gather_kernel<<<MPAD, 256>>>(emb, tagsw, K);
    hardpos_kernel<<<(MPAD + 7) / 8, 256>>>(K, MPAD);
    pairwise_mma_kernel<<<NT * (NT + 1) / 2, 256, SMEM_BYTES>>>(K, NT);
    finalize_kernel<<<1, 1024>>>(K, (float*)d_out);
}

// round 7
// speedup vs baseline: 1.8101x; 1.5861x over previous
#include <cuda_runtime.h>
#include <cuda_fp16.h>
#include <math.h>
#include <stdint.h>

#define D        256
#define MAXN     32768
#define MAXM     8192
#define TILE     128
#define INFBITS  0x7F800000u
#define MARGIN_F 0.075f
#define TIECAP   4096

// ---------------- scratch (__device__ globals: no allocations allowed) ----------------
__device__ unsigned g_keys[MAXN];
__device__ unsigned g_hist1[65536];
__device__ unsigned g_hist2[65536];
__device__ unsigned g_kthhi;
__device__ unsigned g_need1;
__device__ unsigned g_kth;
__device__ int      g_needTies;
__device__ int      g_counter;
__device__ int      g_tiecnt;
__device__ int      g_tielist[TIECAP];
__device__ int      g_is64;
__device__ int      g_selidx[MAXM];
__device__ float    g_emb[MAXM * D];
__device__ __half   g_embh[MAXM * D];
__device__ __half   g_embl[MAXM * D];
__device__ int      g_lab[MAXM];
__device__ float    g_sqn[MAXM];
__device__ float    g_hp[MAXM];
__device__ int      g_poscnt[MAXM];
__device__ unsigned g_negmin[MAXM];
__device__ unsigned g_shnmin[MAXM];

// ---------------- helpers ----------------
__device__ __forceinline__ uint32_t smem_u32(const void* p) {
    uint32_t a;
    asm("{ .reg .u64 t; cvta.to.shared.u64 t, %1; cvt.u32.u64 %0, t; }" : "=r"(a) : "l"(p));
    return a;
}
__device__ __forceinline__ float fsqrt_approx(float x) {
    float r;
    asm("sqrt.approx.f32 %0, %1;" : "=f"(r) : "f"(x));
    return r;
}
#define SW128(off) ((off) ^ (((off) >> 3) & 0x70))

__device__ __forceinline__ void ldsm_x4(uint32_t& r0, uint32_t& r1, uint32_t& r2, uint32_t& r3,
                                        uint32_t addr) {
    asm volatile("ldmatrix.sync.aligned.m8n8.x4.shared.b16 {%0,%1,%2,%3}, [%4];"
                 : "=r"(r0), "=r"(r1), "=r"(r2), "=r"(r3) : "r"(addr));
}
__device__ __forceinline__ void mma16816(float& c0, float& c1, float& c2, float& c3,
                                         uint32_t a0, uint32_t a1, uint32_t a2, uint32_t a3,
                                         uint32_t b0, uint32_t b1) {
    asm volatile(
        "mma.sync.aligned.m16n8k16.row.col.f32.f16.f16.f32 "
        "{%0,%1,%2,%3}, {%4,%5,%6,%7}, {%8,%9}, {%0,%1,%2,%3};"
        : "+f"(c0), "+f"(c1), "+f"(c2), "+f"(c3)
        : "r"(a0), "r"(a1), "r"(a2), "r"(a3), "r"(b0), "r"(b1));
}

// SMEM layout (dynamic) for pairwise
#define SA_H   0
#define SA_L   16384
#define SB_H   32768
#define SB_L   49152
#define SM_LABI 65536
#define SM_SQNI (SM_LABI + 512)
#define SM_HPI  (SM_SQNI + 512)
#define SM_LABJ (SM_HPI + 512)
#define SM_SQNJ (SM_LABJ + 512)
#define SM_HPJ  (SM_SQNJ + 512)
#define SM_RN   (SM_HPJ + 512)
#define SM_RS   (SM_RN + 512)
#define SM_CN   (SM_RS + 512)
#define SM_CS   (SM_CN + 512)
#define SMEM_BYTES (SM_CS + 512)

// ---------------- setup: init mins, zero hists/counters, build keys ----------------
__global__ void setup_kernel(const float* __restrict__ conf, int N, int MPAD) {
    int stride = gridDim.x * blockDim.x;
    int t0 = blockIdx.x * blockDim.x + threadIdx.x;
    for (int i = t0; i < MPAD; i += stride) { g_negmin[i] = INFBITS; g_shnmin[i] = INFBITS; }
    for (int i = t0; i < 65536; i += stride) { g_hist1[i] = 0u; g_hist2[i] = 0u; }
    for (int i = t0; i < N; i += stride) {
        unsigned u = __float_as_uint(conf[i]);
        u = (u & 0x80000000u) ? ~u : (u | 0x80000000u);
        g_keys[i] = u;
    }
    if (t0 == 0) { g_counter = 0; g_tiecnt = 0; }
}

// ---------------- level-1 histogram over high 16 bits ----------------
__global__ void hist1_kernel(int N) {
    for (int i = blockIdx.x * blockDim.x + threadIdx.x; i < N; i += gridDim.x * blockDim.x)
        atomicAdd(&g_hist1[g_keys[i] >> 16], 1u);
}

// ---------------- single-block suffix scan: pick bin where top-count crosses target ----
__device__ void scan_pick(const unsigned* __restrict__ hist, unsigned target,
                          unsigned* outBin, unsigned* outNeed) {
    __shared__ unsigned csum[1024];
    int c = threadIdx.x;            // 1024 chunks x 64 bins
    unsigned mysum = 0;
    int b0 = c * 64;
#pragma unroll 8
    for (int b = 0; b < 64; b++) mysum += hist[b0 + b];
    csum[c] = mysum;
    __syncthreads();
    // inclusive suffix scan: csum[c] = sum_{c'>=c}
    for (int off = 1; off < 1024; off <<= 1) {
        unsigned add = (c + off < 1024) ? csum[c + off] : 0u;
        __syncthreads();
        csum[c] += add;
        __syncthreads();
    }
    unsigned suf = csum[c] - mysum;   // strictly-above-chunk count
    if (suf < target && target <= suf + mysum) {
        unsigned rem = target - suf, cum = 0;
        for (int b = 63; b >= 0; b--) {
            unsigned h = hist[b0 + b];
            if (cum + h >= rem) { *outBin = (unsigned)(b0 + b); *outNeed = rem - cum; break; }
            cum += h;
        }
    }
}

__global__ void scan1_kernel(const int* __restrict__ tagsw, int N, int K) {
    // fold int64-vs-int32 tag detect in here
    __shared__ int sbad;
    if (threadIdx.x == 0) sbad = 0;
    __syncthreads();
    int bad = 0;
    for (int i = threadIdx.x * 2 + 1; i < N; i += 2 * blockDim.x)
        if (tagsw[i] != 0) bad = 1;
    if (bad) atomicOr(&sbad, 1);
    __syncthreads();
    if (threadIdx.x == 0) g_is64 = sbad ? 0 : 1;
    scan_pick(g_hist1, (unsigned)K, &g_kthhi, &g_need1);
}

// ---------------- level-2 histogram over low 16 bits of matching keys ----------------
__global__ void hist2_kernel(int N) {
    unsigned hi = g_kthhi;
    for (int i = blockIdx.x * blockDim.x + threadIdx.x; i < N; i += gridDim.x * blockDim.x) {
        unsigned k = g_keys[i];
        if ((k >> 16) == hi) atomicAdd(&g_hist2[k & 0xFFFFu], 1u);
    }
}

__global__ void scan2_kernel() {
    __shared__ unsigned bin, need;
    scan_pick(g_hist2, g_need1, &bin, &need);
    __syncthreads();   // order the single writer's stores before thread 0 reads
    if (threadIdx.x == 0) { g_kth = (g_kthhi << 16) | bin; g_needTies = (int)need; }
}

// ---------------- compact (>) + collect ties (==) ----------------
__global__ void compact_kernel(int N) {
    unsigned kth = g_kth;
    for (int i = blockIdx.x * blockDim.x + threadIdx.x; i < N; i += gridDim.x * blockDim.x) {
        unsigned k = g_keys[i];
        if (k > kth) {
            int p = atomicAdd(&g_counter, 1);
            g_selidx[p] = i;
        } else if (k == kth) {
            int p = atomicAdd(&g_tiecnt, 1);
            if (p < TIECAP) g_tielist[p] = i;
        }
    }
}

// ---------------- ties: stable -> lowest indices win ----------------
__global__ void ties_kernel(int N) {
    if (threadIdx.x != 0) return;
    int need = g_needTies;
    int base = g_counter;
    int tc = g_tiecnt;
    if (tc <= TIECAP) {
        int last = -1;
        for (int r = 0; r < need; r++) {
            int best = 0x7FFFFFFF;
            for (int t = 0; t < tc; t++) {
                int v = g_tielist[t];
                if (v > last && v < best) best = v;
            }
            g_selidx[base + r] = best;
            last = best;
        }
    } else {
        unsigned kth = g_kth;
        int taken = 0;
        for (int i = 0; i < N && taken < need; i++)
            if (g_keys[i] == kth) g_selidx[base + taken++] = i;
    }
}

// ---------------- gather + fp16 hi/lo split ----------------
__global__ void gather_kernel(const float* __restrict__ emb, const int* __restrict__ tagsw, int K) {
    __shared__ float red[256];
    int m = blockIdx.x;
    int t = threadIdx.x;
    int idx = (m < K) ? g_selidx[m] : 0;
    float v = (m < K) ? emb[(size_t)idx * D + t] : 0.f;
    g_emb[m * D + t] = v;
    __half hi = __float2half_rn(v);
    __half lo = __float2half_rn(v - __half2float(hi));
    g_embh[m * D + t] = hi;
    g_embl[m * D + t] = lo;
    red[t] = v * v;
    __syncthreads();
    for (int s = 128; s > 0; s >>= 1) {
        if (t < s) red[t] += red[t + s];
        __syncthreads();
    }
    if (t == 0) {
        g_sqn[m] = (m < K) ? red[0] : 0.f;
        int lab = -1;
        if (m < K) lab = g_is64 ? tagsw[2 * idx] : tagsw[idx];
        g_lab[m] = lab;
    }
}

// ---------------- hard positives (fp32 exact, sparse) ----------------
__global__ void hardpos_kernel(int K, int MPAD) {
    __shared__ int slab[MAXM];
    for (int i = threadIdx.x; i < K; i += blockDim.x) slab[i] = g_lab[i];
    __syncthreads();
    int w = threadIdx.x >> 5, lane = threadIdx.x & 31;
    int a = blockIdx.x * 8 + w;
    if (a >= MPAD) return;
    if (a >= K) {
        if (lane == 0) { g_hp[a] = __uint_as_float(0xFF800000u); g_poscnt[a] = 0; }
        return;
    }
    int la = slab[a];
    float na = g_sqn[a];
    const float4* ea = (const float4*)(g_emb + a * D);
    float mx = __uint_as_float(0xFF800000u);
    int cnt = 0;
    for (int j = lane; j < K; j += 32) {
        if (j != a && slab[j] == la) {
            const float4* ej = (const float4*)(g_emb + j * D);
            float dot = 0.f;
#pragma unroll 8
            for (int q = 0; q < D / 4; q++) {
                float4 x = ea[q], y = ej[q];
                dot += x.x * y.x; dot += x.y * y.y; dot += x.z * y.z; dot += x.w * y.w;
            }
            float sq = na + g_sqn[j] - 2.f * dot;
            float d = sqrtf(fmaxf(sq, 0.f));
            mx = fmaxf(mx, d);
            cnt++;
        }
    }
    for (int o = 16; o; o >>= 1) {
        mx = fmaxf(mx, __shfl_xor_sync(0xffffffffu, mx, o));
        cnt += __shfl_xor_sync(0xffffffffu, cnt, o);
    }
    if (lane == 0) {
        g_hp[a] = cnt ? mx : __uint_as_float(0xFF800000u);
        g_poscnt[a] = cnt;
    }
}

// ---------------- mma.sync pairwise: fp16 2-term split, fused epilogue ----------------
__global__ __launch_bounds__(256)
void pairwise_mma_kernel(int KSEL, int NT) {
    extern __shared__ char smem[];
    uint32_t sb = smem_u32(smem);
    int tid = threadIdx.x, wid = tid >> 5, lane = tid & 31;

    int t = blockIdx.x;
    float nf = (float)NT;
    int bi = (int)(nf + 0.5f - sqrtf((nf + 0.5f) * (nf + 0.5f) - 2.0f * (float)t));
    while (bi > 0 && bi * NT - (bi * (bi - 1)) / 2 > t) bi--;
    while ((bi + 1) * NT - ((bi + 1) * bi) / 2 <= t) bi++;
    int bj = bi + (t - (bi * NT - (bi * (bi - 1)) / 2));
    int gibase = bi * TILE, gjbase = bj * TILE;

    if (tid < 128) {
        int gi = gibase + tid, gj = gjbase + tid;
        ((int*)(smem + SM_LABI))[tid]    = g_lab[gi];
        ((float*)(smem + SM_SQNI))[tid]  = g_sqn[gi];
        ((float*)(smem + SM_HPI))[tid]   = g_hp[gi];
        ((int*)(smem + SM_LABJ))[tid]    = g_lab[gj];
        ((float*)(smem + SM_SQNJ))[tid]  = g_sqn[gj];
        ((float*)(smem + SM_HPJ))[tid]   = g_hp[gj];
        ((unsigned*)(smem + SM_RN))[tid] = INFBITS;
        ((unsigned*)(smem + SM_RS))[tid] = INFBITS;
        ((unsigned*)(smem + SM_CN))[tid] = INFBITS;
        ((unsigned*)(smem + SM_CS))[tid] = INFBITS;
    }

    int mi = wid & 1;
    int nj = wid >> 1;
    int R = mi * 64, C = nj * 32;

    float acc[4][4][4];
#pragma unroll
    for (int a = 0; a < 4; a++)
#pragma unroll
        for (int b = 0; b < 4; b++)
#pragma unroll
            for (int c = 0; c < 4; c++) acc[a][b][c] = 0.f;

    const uint32_t toff[4] = {SA_H, SA_L, SB_H, SB_L};

    for (int ch = 0; ch < 4; ch++) {
        for (int u = tid; u < 4096; u += 256) {
            int tile = u >> 10;
            int v = u & 1023;
            int row = v >> 3;
            int seg = v & 7;
            int base = (tile < 2) ? gibase : gjbase;
            const __half* src = (tile & 1) ? g_embl : g_embh;
            uint4 val = *(const uint4*)(src + (size_t)(base + row) * D + ch * 64 + seg * 8);
            *(uint4*)(smem + toff[tile] + SW128((uint32_t)(row * 128 + seg * 16))) = val;
        }
        __syncthreads();

        int lrow = lane & 15;
        int lk16 = (lane >> 4) * 16;
#pragma unroll
        for (int ks = 0; ks < 4; ks++) {
            int ko = ks * 32 + lk16;
            uint32_t ah[4][4], al[4][4], bh[2][4], bl[2][4];
#pragma unroll
            for (int mf = 0; mf < 4; mf++) {
                uint32_t addr = sb + SW128((uint32_t)((R + mf * 16 + lrow) * 128 + ko));
                ldsm_x4(ah[mf][0], ah[mf][1], ah[mf][2], ah[mf][3], SA_H + addr);
                ldsm_x4(al[mf][0], al[mf][1], al[mf][2], al[mf][3], SA_L + addr);
            }
#pragma unroll
            for (int h = 0; h < 2; h++) {
                uint32_t addr = sb + SW128((uint32_t)((C + h * 16 + lrow) * 128 + ko));
                ldsm_x4(bh[h][0], bh[h][1], bh[h][2], bh[h][3], SB_H + addr);
                ldsm_x4(bl[h][0], bl[h][1], bl[h][2], bl[h][3], SB_L + addr);
            }
#pragma unroll
            for (int mf = 0; mf < 4; mf++) {
#pragma unroll
                for (int nfr = 0; nfr < 4; nfr++) {
                    int h = nfr >> 1, s = nfr & 1;
                    uint32_t bh0 = bh[h][s], bh1 = bh[h][s + 2];
                    uint32_t bl0 = bl[h][s], bl1 = bl[h][s + 2];
                    float* cc = acc[mf][nfr];
                    mma16816(cc[0], cc[1], cc[2], cc[3],
                             ah[mf][0], ah[mf][1], ah[mf][2], ah[mf][3], bh0, bh1);
                    mma16816(cc[0], cc[1], cc[2], cc[3],
                             ah[mf][0], ah[mf][1], ah[mf][2], ah[mf][3], bl0, bl1);
                    mma16816(cc[0], cc[1], cc[2], cc[3],
                             al[mf][0], al[mf][1], al[mf][2], al[mf][3], bh0, bh1);
                }
            }
        }
        __syncthreads();
    }

    // ---------------- fused epilogue ----------------
    const float INFv = __uint_as_float(INFBITS);
    const int*   sLabI = (const int*)(smem + SM_LABI);
    const float* sSqnI = (const float*)(smem + SM_SQNI);
    const float* sHpI  = (const float*)(smem + SM_HPI);
    const int*   sLabJ = (const int*)(smem + SM_LABJ);
    const float* sSqnJ = (const float*)(smem + SM_SQNJ);
    const float* sHpJ  = (const float*)(smem + SM_HPJ);
    unsigned* sRN = (unsigned*)(smem + SM_RN);
    unsigned* sRS = (unsigned*)(smem + SM_RS);
    unsigned* sCN = (unsigned*)(smem + SM_CN);
    unsigned* sCS = (unsigned*)(smem + SM_CS);

    int lr = lane >> 2, tig = lane & 3;

    float colN[4][2], colS[4][2];
#pragma unroll
    for (int a = 0; a < 4; a++) { colN[a][0] = INFv; colN[a][1] = INFv; colS[a][0] = INFv; colS[a][1] = INFv; }

    int   cloc[4][2]; bool cok[4][2]; int clab[4][2]; float csq[4][2], chp[4][2];
#pragma unroll
    for (int nfr = 0; nfr < 4; nfr++)
#pragma unroll
        for (int p = 0; p < 2; p++) {
            int cl = C + nfr * 8 + 2 * tig + p;
            cloc[nfr][p] = cl;
            cok[nfr][p] = (gjbase + cl) < KSEL;
            clab[nfr][p] = sLabJ[cl];
            csq[nfr][p] = sSqnJ[cl];
            chp[nfr][p] = sHpJ[cl];
        }

#pragma unroll
    for (int mf = 0; mf < 4; mf++) {
        int r0 = R + mf * 16 + lr, r1 = r0 + 8;
        bool ok0 = (gibase + r0) < KSEL, ok1 = (gibase + r1) < KSEL;
        int   lab0 = sLabI[r0], lab1 = sLabI[r1];
        float sq0 = sSqnI[r0], sq1 = sSqnI[r1];
        float hp0 = sHpI[r0],  hp1 = sHpI[r1];
        float rN0 = INFv, rS0 = INFv, rN1 = INFv, rS1 = INFv;
#pragma unroll
        for (int nfr = 0; nfr < 4; nfr++) {
#pragma unroll
            for (int p = 0; p < 2; p++) {
                bool okc = cok[nfr][p];
                int lc = clab[nfr][p];
                float nc = csq[nfr][p], hc = chp[nfr][p];
                if (ok0 && okc && lab0 != lc) {
                    float sq = sq0 + nc - 2.f * acc[mf][nfr][p];
                    float dd = fsqrt_approx(fmaxf(sq, 0.f));
                    rN0 = fminf(rN0, dd);
                    if (dd > hp0) rS0 = fminf(rS0, dd);
                    colN[nfr][p] = fminf(colN[nfr][p], dd);
                    if (dd > hc) colS[nfr][p] = fminf(colS[nfr][p], dd);
                }
                if (ok1 && okc && lab1 != lc) {
                    float sq = sq1 + nc - 2.f * acc[mf][nfr][2 + p];
                    float dd = fsqrt_approx(fmaxf(sq, 0.f));
                    rN1 = fminf(rN1, dd);
                    if (dd > hp1) rS1 = fminf(rS1, dd);
                    colN[nfr][p] = fminf(colN[nfr][p], dd);
                    if (dd > hc) colS[nfr][p] = fminf(colS[nfr][p], dd);
                }
            }
        }
#pragma unroll
        for (int o = 1; o <= 2; o <<= 1) {
            rN0 = fminf(rN0, __shfl_xor_sync(0xffffffffu, rN0, o));
            rS0 = fminf(rS0, __shfl_xor_sync(0xffffffffu, rS0, o));
            rN1 = fminf(rN1, __shfl_xor_sync(0xffffffffu, rN1, o));
            rS1 = fminf(rS1, __shfl_xor_sync(0xffffffffu, rS1, o));
        }
        if (tig == 0) {
            if (rN0 < INFv) atomicMin(&sRN[r0], __float_as_uint(rN0));
            if (rS0 < INFv) atomicMin(&sRS[r0], __float_as_uint(rS0));
            if (rN1 < INFv) atomicMin(&sRN[r1], __float_as_uint(rN1));
            if (rS1 < INFv) atomicMin(&sRS[r1], __float_as_uint(rS1));
        }
    }
#pragma unroll
    for (int a = 0; a < 4; a++)
#pragma unroll
        for (int p = 0; p < 2; p++) {
#pragma unroll
            for (int o = 4; o <= 16; o <<= 1) {
                colN[a][p] = fminf(colN[a][p], __shfl_xor_sync(0xffffffffu, colN[a][p], o));
                colS[a][p] = fminf(colS[a][p], __shfl_xor_sync(0xffffffffu, colS[a][p], o));
            }
        }
    if (lane < 4) {
#pragma unroll
        for (int a = 0; a < 4; a++)
#pragma unroll
            for (int p = 0; p < 2; p++) {
                int cl = cloc[a][p];
                if (colN[a][p] < INFv) atomicMin(&sCN[cl], __float_as_uint(colN[a][p]));
                if (colS[a][p] < INFv) atomicMin(&sCS[cl], __float_as_uint(colS[a][p]));
            }
    }
    __syncthreads();
    if (tid < 128) {
        int gi = gibase + tid, gj = gjbase + tid;
        if (gi < KSEL) {
            unsigned a = sRN[tid], b = sRS[tid];
            if (a != INFBITS) atomicMin(&g_negmin[gi], a);
            if (b != INFBITS) atomicMin(&g_shnmin[gi], b);
        }
        if (gj < KSEL) {
            unsigned a = sCN[tid], b = sCS[tid];
            if (a != INFBITS) atomicMin(&g_negmin[gj], a);
            if (b != INFBITS) atomicMin(&g_shnmin[gj], b);
        }
    }
}

// ---------------- finalize ----------------
__global__ void finalize_kernel(int KSEL, float* __restrict__ out) {
    __shared__ float ssum[32];
    __shared__ int scnt[32];
    float sum = 0.f; int cnt = 0;
    for (int a = threadIdx.x; a < KSEL; a += blockDim.x) {
        int pc = g_poscnt[a];
        if (pc > 0 && (KSEL - 1 - pc) > 0) {
            float hp = g_hp[a];
            unsigned sbb = g_shnmin[a];
            float hn = (sbb != INFBITS) ? __uint_as_float(sbb) : __uint_as_float(g_negmin[a]);
            float per = hp - hn + MARGIN_F;
            if (per < 0.f) per = 0.f;
            sum += per; cnt++;
        }
    }
    for (int o = 16; o; o >>= 1) {
        sum += __shfl_xor_sync(0xffffffffu, sum, o);
        cnt += __shfl_xor_sync(0xffffffffu, cnt, o);
    }
    int w = threadIdx.x >> 5, lane = threadIdx.x & 31;
    if (lane == 0) { ssum[w] = sum; scnt[w] = cnt; }
    __syncthreads();
    if (threadIdx.x < 32) {
        int nw = blockDim.x >> 5;
        sum = (threadIdx.x < nw) ? ssum[threadIdx.x] : 0.f;
        cnt = (threadIdx.x < nw) ? scnt[threadIdx.x] : 0;
        for (int o = 16; o; o >>= 1) {
            sum += __shfl_xor_sync(0xffffffffu, sum, o);
            cnt += __shfl_xor_sync(0xffffffffu, cnt, o);
        }
        if (threadIdx.x == 0) out[0] = (cnt > 0) ? sum / (float)cnt : 0.f;
    }
}

// ---------------- launch ----------------
extern "C" void kernel_launch(void* const* d_in, const int* in_sizes, int n_in,
                              void* d_out, int out_size) {
    const float* emb   = (const float*)d_in[0];
    const int*   tagsw = (const int*)d_in[1];
    const float* conf  = (const float*)d_in[2];
    int N = in_sizes[2];
    int K = (int)(0.2 * (double)N);
    int NT = (K + TILE - 1) / TILE;
    int MPAD = NT * TILE;

    cudaFuncSetAttribute(pairwise_mma_kernel, cudaFuncAttributeMaxDynamicSharedMemorySize, SMEM_BYTES);

    setup_kernel<<<128, 256>>>(conf, N, MPAD);
    hist1_kernel<<<64, 256>>>(N);
    scan1_kernel<<<1, 1024>>>(tagsw, N, K);
    hist2_kernel<<<64, 256>>>(N);
    scan2_kernel<<<1, 1024>>>();
    compact_kernel<<<64, 256>>>(N);
    ties_kernel<<<1, 32>>>(N);
    gather_kernel<<<MPAD, 256>>>(emb, tagsw, K);
    hardpos_kernel<<<(MPAD + 7) / 8, 256>>>(K, MPAD);
    pairwise_mma_kernel<<<NT * (NT + 1) / 2, 256, SMEM_BYTES>>>(K, NT);
    finalize_kernel<<<1, 1024>>>(K, (float*)d_out);
}